// round 13
// baseline (speedup 1.0000x reference)
#include <cuda_runtime.h>
#include <cuda_bf16.h>
#include <math.h>
#include <stdint.h>

#define Dd 256
#define Vv 3000
#define Tt 50
#define Kk 50
#define Ll 300
#define LPAD 320

// ---------------- scratch (__device__ globals; no allocations) --------------
static __device__ __align__(16) __nv_bfloat16 g_Pbf[12800 * 3000];   // exp(logits), bf16
static __device__ __align__(16) __nv_bfloat16 g_Abf[12800 * LPAD];
static __device__ __align__(16) __nv_bfloat16 g_rhoBf[3000 * LPAD];
static __device__ float g_S[12800];          // softmax denominators
static __device__ float g_x[50 * 200];
static __device__ float g_xw0[50 * 800];
static __device__ float g_xw1[50 * 800];
static __device__ float g_hs0[50 * 200];
static __device__ float g_hs1[50 * 200];
static __device__ float g_etas[50 * 50];
static __device__ float g_projMu[50 * 50];
static __device__ float g_projLs[50 * 50];
static __device__ float g_cat[256 * 3050];
static __device__ float g_h1[256 * 800];
static __device__ float g_h2[256 * 800];
static __device__ float g_muth[256 * 50];
static __device__ float g_lsth[256 * 50];
static __device__ float g_theta[256 * 50];
static __device__ float g_scalars[4];        // 0:+sum(log*bows) 1:kl_a 2:kl_eta 3:kl_th

// ---------------- fast exp on FMA pipe --------------------------------------
__device__ __forceinline__ float fexp_fast(float x) {
    float y = x * 1.4426950408889634f;
    float r = rintf(y);
    float f = y - r;
    float p = 1.3333558e-3f;
    p = fmaf(p, f, 9.6181291e-3f);
    p = fmaf(p, f, 5.5504109e-2f);
    p = fmaf(p, f, 2.4022651e-1f);
    p = fmaf(p, f, 6.9314718e-1f);
    p = fmaf(p, f, 1.0f);
    return p * __int_as_float(((int)r + 127) << 23);
}

__device__ __forceinline__ float blockReduceSum(float v, float* sm) {
    int tid = threadIdx.x;
    sm[tid] = v; __syncthreads();
    for (int off = blockDim.x >> 1; off > 0; off >>= 1) {
        if (tid < off) sm[tid] += sm[tid + off];
        __syncthreads();
    }
    return sm[0];
}

__device__ __forceinline__ void cp16(uint32_t dst, const void* src, int szok) {
    asm volatile("cp.async.cg.shared.global [%0], [%1], 16, %2;"
                 :: "r"(dst), "l"(src), "r"(szok) : "memory");
}

// ---------------- big GEMM on HMMA (mma.sync bf16) + exp epilogue -----------
#define BSTR 328
#define GEMM_SMEM (2 * 128 * BSTR * 2)

extern __shared__ __nv_bfloat16 dynsm[];

__global__ void __launch_bounds__(256, 1) gemmExpMMA(
    const __nv_bfloat16* __restrict__ Abf, const __nv_bfloat16* __restrict__ Bbf,
    __nv_bfloat16* __restrict__ Pbf, float* __restrict__ rowsum) {
    __nv_bfloat16* A_sm = dynsm;
    __nv_bfloat16* B_sm = dynsm + 128 * BSTR;

    const int tid = threadIdx.x;
    const int wid = tid >> 5, lane = tid & 31;
    const int warp_m = wid >> 2, warp_n = wid & 3;
    const int m_base = warp_m * 64, n_base = warp_n * 32;

    const int row0 = blockIdx.y * 128;
    const int col0 = blockIdx.x * 128;

    const uint32_t aBase = (uint32_t)__cvta_generic_to_shared(A_sm);
    const uint32_t bBase = (uint32_t)__cvta_generic_to_shared(B_sm);

    auto issue_chunk = [&](int c) {
#pragma unroll
        for (int it = 0; it < 5; it++) {
            int idx = tid + it * 256;
            int r = idx / 10, seg = idx - r * 10;
            uint32_t off = (uint32_t)((r * BSTR + c * 80 + seg * 8) * 2);
            cp16(aBase + off,
                 &Abf[(size_t)(row0 + r) * LPAD + c * 80 + seg * 8], 16);
            int n = col0 + r;
            cp16(bBase + off,
                 &Bbf[(size_t)(n < Vv ? n : Vv - 1) * LPAD + c * 80 + seg * 8],
                 n < Vv ? 16 : 0);
        }
        asm volatile("cp.async.commit_group;" ::: "memory");
    };

    issue_chunk(0);
    issue_chunk(1);

    float acc[4][4][4];
#pragma unroll
    for (int i = 0; i < 4; i++)
#pragma unroll
        for (int j = 0; j < 4; j++)
#pragma unroll
            for (int e = 0; e < 4; e++) acc[i][j][e] = 0.f;

#pragma unroll
    for (int c = 0; c < 4; c++) {
        if (c < 3) asm volatile("cp.async.wait_group 1;" ::: "memory");
        else       asm volatile("cp.async.wait_group 0;" ::: "memory");
        __syncthreads();
#pragma unroll
        for (int i = 0; i < 5; i++) {
            const int ks = c * 5 + i;
            uint32_t afr[4][4], bfr[4][2];
#pragma unroll
            for (int mi = 0; mi < 4; mi++) {
                uint32_t addr = aBase + (uint32_t)(((m_base + mi * 16 + (lane & 15)) * BSTR
                                 + ks * 16 + (lane >> 4) * 8) * 2);
                asm volatile(
                    "ldmatrix.sync.aligned.m8n8.x4.shared.b16 {%0,%1,%2,%3}, [%4];"
                    : "=r"(afr[mi][0]), "=r"(afr[mi][1]), "=r"(afr[mi][2]), "=r"(afr[mi][3])
                    : "r"(addr));
            }
#pragma unroll
            for (int ni = 0; ni < 4; ni++) {
                uint32_t addr = bBase + (uint32_t)(((n_base + ni * 8 + (lane & 7)) * BSTR
                                 + ks * 16 + ((lane >> 3) & 1) * 8) * 2);
                asm volatile(
                    "ldmatrix.sync.aligned.m8n8.x2.shared.b16 {%0,%1}, [%2];"
                    : "=r"(bfr[ni][0]), "=r"(bfr[ni][1])
                    : "r"(addr));
            }
#pragma unroll
            for (int mi = 0; mi < 4; mi++)
#pragma unroll
                for (int ni = 0; ni < 4; ni++) {
                    asm volatile(
                        "mma.sync.aligned.m16n8k16.row.col.f32.bf16.bf16.f32 "
                        "{%0,%1,%2,%3}, {%4,%5,%6,%7}, {%8,%9}, {%0,%1,%2,%3};"
                        : "+f"(acc[mi][ni][0]), "+f"(acc[mi][ni][1]),
                          "+f"(acc[mi][ni][2]), "+f"(acc[mi][ni][3])
                        : "r"(afr[mi][0]), "r"(afr[mi][1]), "r"(afr[mi][2]), "r"(afr[mi][3]),
                          "r"(bfr[ni][0]), "r"(bfr[ni][1]));
                }
        }
        if (c + 2 < 4) issue_chunk(c + 2);
    }

    const int g = lane >> 2, q = lane & 3;
#pragma unroll
    for (int mi = 0; mi < 4; mi++) {
        float rsLo = 0.f, rsHi = 0.f;
        int rLo = row0 + m_base + mi * 16 + g;
#pragma unroll
        for (int ni = 0; ni < 4; ni++) {
            int col = col0 + n_base + ni * 8 + q * 2;
            if (col < Vv) {
                __nv_bfloat162 bLo = __floats2bfloat162_rn(
                    fexp_fast(acc[mi][ni][0]), fexp_fast(acc[mi][ni][1]));
                __nv_bfloat162 bHi = __floats2bfloat162_rn(
                    fexp_fast(acc[mi][ni][2]), fexp_fast(acc[mi][ni][3]));
                rsLo += __low2float(bLo) + __high2float(bLo);
                rsHi += __low2float(bHi) + __high2float(bHi);
                *(__nv_bfloat162*)&Pbf[(size_t)rLo * Vv + col] = bLo;
                *(__nv_bfloat162*)&Pbf[(size_t)(rLo + 8) * Vv + col] = bHi;
            }
        }
        rsLo += __shfl_xor_sync(0xffffffffu, rsLo, 1);
        rsLo += __shfl_xor_sync(0xffffffffu, rsLo, 2);
        rsHi += __shfl_xor_sync(0xffffffffu, rsHi, 1);
        rsHi += __shfl_xor_sync(0xffffffffu, rsHi, 2);
        if (q == 0) {
            atomicAdd(&rowsum[rLo], rsLo);
            atomicAdd(&rowsum[rLo + 8], rsHi);
        }
    }
}

// ---------------- build bf16 operands ---------------------------------------
__global__ void buildABfK(const float* __restrict__ alpha, const float* __restrict__ lam,
                          const int* __restrict__ times, const int* __restrict__ sources) {
    int stride = gridDim.x * blockDim.x;
    for (int i = blockIdx.x * blockDim.x + threadIdx.x; i < 12800 * LPAD; i += stride) {
        int r = i / LPAD, l = i - r * LPAD;
        int d = r / Kk, k = r - d * Kk;
        float v = 0.f;
        if (l < Ll)
            v = alpha[((size_t)k * Tt + times[d]) * Ll + l] * lam[(size_t)sources[d] * Ll + l];
        g_Abf[i] = __float2bfloat16(v);
    }
}

__global__ void rhoBfK(const float* __restrict__ rho) {
    int stride = gridDim.x * blockDim.x;
    for (int i = blockIdx.x * blockDim.x + threadIdx.x; i < Vv * LPAD; i += stride) {
        int r = i / LPAD, l = i - r * LPAD;
        g_rhoBf[i] = __float2bfloat16(l < Ll ? rho[(size_t)r * Ll + l] : 0.f);
    }
}

// ---------------- zero scratch (split-K outputs + accumulators) -------------
__global__ void zeroAllK() {
    int stride = gridDim.x * blockDim.x;
    for (int i = blockIdx.x * blockDim.x + threadIdx.x; i < 204800; i += stride) {
        g_h1[i] = 0.f;
        if (i < 12800) { g_S[i] = 0.f; g_muth[i] = 0.f; g_lsth[i] = 0.f; }
        if (i < 4) g_scalars[i] = 0.f;
    }
}

// ---------------- kl_alpha --------------------------------------------------
__global__ void klAlphaK(const float* __restrict__ mu, const float* __restrict__ ls) {
    __shared__ float sm[256];
    const float logdelta = logf(0.005f);
    const float invdel = 1.f / (__expf(logdelta) + 1e-6f);
    int stride = gridDim.x * blockDim.x;
    float acc = 0.f;
    for (int i = blockIdx.x * blockDim.x + threadIdx.x; i < Kk * Tt * Ll; i += stride) {
        int t = (i / Ll) % Tt;
        float qm = mu[i], ql = ls[i];
        if (t == 0) {
            acc += (__expf(ql) + qm * qm) / (1.f + 1e-6f) - 1.f - ql;
        } else {
            float pm = mu[i - Ll];
            float d = qm - pm;
            acc += (__expf(ql) + d * d) * invdel - 1.f + logdelta - ql;
        }
    }
    float tot = blockReduceSum(acc, sm);
    if (threadIdx.x == 0) atomicAdd(&g_scalars[1], 0.5f * tot);
}

// ---------------- generic tiled GEMM (NN, split-K atomic, opt fused bias) ---
__global__ void gemmNN(const float* __restrict__ A, const float* __restrict__ B,
                       float* __restrict__ C, int M, int N, int Kd, int kchunk,
                       const float* __restrict__ bias, int relu) {
    __shared__ float As[16][64];
    __shared__ float Bs[16][64];
    int tid = threadIdx.x;
    int tx = tid & 15, ty = tid >> 4;
    int row0 = blockIdx.y * 64, col0 = blockIdx.x * 64;
    int kbeg = blockIdx.z * kchunk;
    int kend = min(Kd, kbeg + kchunk);
    int aRow = tid >> 2, aCol = (tid & 3) << 2;
    int bRow = tid >> 4, bCol = (tid & 15) << 2;
    float acc[4][4] = {};
    for (int k0 = kbeg; k0 < kend; k0 += 16) {
#pragma unroll
        for (int i = 0; i < 4; i++) {
            int kk = k0 + aCol + i, r = row0 + aRow;
            As[aCol + i][aRow] = (r < M && kk < kend) ? A[(size_t)r * Kd + kk] : 0.f;
        }
#pragma unroll
        for (int i = 0; i < 4; i++) {
            int kk = k0 + bRow, n = col0 + bCol + i;
            Bs[bRow][bCol + i] = (n < N && kk < kend) ? B[(size_t)kk * N + n] : 0.f;
        }
        __syncthreads();
#pragma unroll
        for (int kk = 0; kk < 16; kk++) {
            float a[4], b[4];
#pragma unroll
            for (int i = 0; i < 4; i++) a[i] = As[kk][ty * 4 + i];
#pragma unroll
            for (int j = 0; j < 4; j++) b[j] = Bs[kk][tx * 4 + j];
#pragma unroll
            for (int i = 0; i < 4; i++)
#pragma unroll
                for (int j = 0; j < 4; j++) acc[i][j] = fmaf(a[i], b[j], acc[i][j]);
        }
        __syncthreads();
    }
#pragma unroll
    for (int i = 0; i < 4; i++) {
        int r = row0 + ty * 4 + i;
        if (r >= M) continue;
#pragma unroll
        for (int j = 0; j < 4; j++) {
            int c = col0 + tx * 4 + j;
            if (c >= N) continue;
            if (gridDim.z > 1) atomicAdd(&C[(size_t)r * N + c], acc[i][j]);
            else {
                float v = acc[i][j];
                if (bias) v += bias[c];
                if (relu) v = fmaxf(v, 0.f);
                C[(size_t)r * N + c] = v;
            }
        }
    }
}

// ---------------- bias (+optional relu) -------------------------------------
__global__ void biasActK(float* __restrict__ C, const float* __restrict__ b,
                         int M, int N, int relu) {
    int stride = gridDim.x * blockDim.x;
    for (int i = blockIdx.x * blockDim.x + threadIdx.x; i < M * N; i += stride) {
        float v = C[i] + b[i % N];
        if (relu) v = fmaxf(v, 0.f);
        C[i] = v;
    }
}

// ---------------- LSTM: reg Whh (bf16x2) + smem xw + fast activations -------
__device__ __forceinline__ unsigned ctarank_() {
    unsigned r; asm("mov.u32 %0, %%cluster_ctarank;" : "=r"(r)); return r;
}
__device__ __forceinline__ void cluster_sync_() {
    asm volatile("barrier.cluster.arrive.aligned;" ::: "memory");
    asm volatile("barrier.cluster.wait.aligned;" ::: "memory");
}
__device__ __forceinline__ float sigmoid_fast(float x) {
    return __fdividef(1.f, 1.f + __expf(-x));
}
__device__ __forceinline__ float tanh_fast(float x) {
    return __fdividef(2.f, 1.f + __expf(-2.f * x)) - 1.f;
}

__global__ void __launch_bounds__(512, 1) __cluster_dims__(4, 1, 1)
lstmK(const float* __restrict__ xw, const float* __restrict__ Whh,
      float* __restrict__ hs) {
    __shared__ float xws[10000];               // this CTA's 50x200 xw slice (40KB)
    __shared__ __align__(16) float hA[256];
    __shared__ __align__(16) float hB[256];
    __shared__ float pbuf[512];
    int tid = threadIdx.x;
    unsigned rank = ctarank_();

    int j = tid % 200;
    int half = (tid < 400) ? (tid / 200) : 0;
    int col = (j / 50) * 200 + (int)rank * 50 + (j % 50);

    uint32_t w2[50];
    if (tid < 400) {
#pragma unroll
        for (int i = 0; i < 50; i++) {
            float f0 = Whh[(size_t)(half * 100 + 2 * i) * 800 + col];
            float f1 = Whh[(size_t)(half * 100 + 2 * i + 1) * 800 + col];
            __nv_bfloat162 b2 = __floats2bfloat162_rn(f0, f1);
            w2[i] = *(uint32_t*)&b2;
        }
    }
    // preload xw slice: xws[t*200 + jl] = xw[t*800 + col(jl)]
    for (int idx = tid; idx < 10000; idx += 512) {
        int t = idx / 200, jl = idx - t * 200;
        int cj = (jl / 50) * 200 + (int)rank * 50 + (jl % 50);
        xws[idx] = xw[t * 800 + cj];
    }
    if (tid < 200) hA[tid] = 0.f;
    float c = 0.f;
    __syncthreads();
    cluster_sync_();

    const uint32_t hAaddr = (uint32_t)__cvta_generic_to_shared(hA);
    const uint32_t hBaddr = (uint32_t)__cvta_generic_to_shared(hB);

    for (int t = 0; t < Tt; t++) {
        const float4* hv4 = (const float4*)((t & 1) ? hB : hA);
        const uint32_t hwaddr = (t & 1) ? hAaddr : hBaddr;
        if (tid < 400) {
            float p0 = 0.f, p1 = 0.f;
            const float4* hh4 = hv4 + half * 25;
#pragma unroll
            for (int i = 0; i < 25; i++) {
                float4 hh = hh4[i];
                uint32_t wa = w2[2 * i], wb = w2[2 * i + 1];
                p0 = fmaf(hh.x, __int_as_float(wa << 16), p0);
                p1 = fmaf(hh.y, __int_as_float(wa & 0xffff0000u), p1);
                p0 = fmaf(hh.z, __int_as_float(wb << 16), p0);
                p1 = fmaf(hh.w, __int_as_float(wb & 0xffff0000u), p1);
            }
            pbuf[tid] = p0 + p1;
        }
        __syncthreads();
        if (tid < 50) {
            int base = t * 200;
            float gi = xws[base + tid]       + pbuf[tid]       + pbuf[tid + 200];
            float gf = xws[base + 50 + tid]  + pbuf[50 + tid]  + pbuf[250 + tid];
            float gg = xws[base + 100 + tid] + pbuf[100 + tid] + pbuf[300 + tid];
            float go = xws[base + 150 + tid] + pbuf[150 + tid] + pbuf[350 + tid];
            c = sigmoid_fast(gf) * c + sigmoid_fast(gi) * tanh_fast(gg);
            float h2 = sigmoid_fast(go) * tanh_fast(c);
            int e = (int)rank * 50 + tid;
            hs[t * 200 + e] = h2;
            uint32_t la = hwaddr + (uint32_t)(e * 4);
#pragma unroll
            for (unsigned r2 = 0; r2 < 4; r2++) {
                uint32_t ra;
                asm volatile("mapa.shared::cluster.u32 %0, %1, %2;"
                             : "=r"(ra) : "r"(la), "r"(r2));
                asm volatile("st.shared::cluster.f32 [%0], %1;"
                             :: "r"(ra), "f"(h2) : "memory");
            }
        }
        cluster_sync_();
    }
}

// ---------------- eta scan: only the 50x50 recurrence is sequential ---------
__global__ void etaScanK(const float* __restrict__ projMu, const float* __restrict__ projLs,
                         const float* __restrict__ Wmu, const float* __restrict__ Wls) {
    __shared__ float sWm[2500], sWl[2500];
    __shared__ float eta[50], muv[50], lsv[50], red[50];
    __shared__ float klacc;
    int tid = threadIdx.x;   // 128
    for (int i = tid; i < 2500; i += 128) {
        sWm[i] = Wmu[10000 + i];
        sWl[i] = Wls[10000 + i];
    }
    if (tid < 50) eta[tid] = 0.f;
    if (tid == 0) klacc = 0.f;
    const float logdelta = logf(0.005f);
    __syncthreads();
    for (int t = 0; t < Tt; t++) {
        if (tid < 50) {
            float m = projMu[t * 50 + tid];
#pragma unroll 10
            for (int jj = 0; jj < 50; jj++) m = fmaf(eta[jj], sWm[jj * 50 + tid], m);
            muv[tid] = m;
        } else if (tid >= 64 && tid < 114) {
            int k = tid - 64;
            float m = projLs[t * 50 + k];
#pragma unroll 10
            for (int jj = 0; jj < 50; jj++) m = fmaf(eta[jj], sWl[jj * 50 + k], m);
            lsv[k] = m;
        }
        __syncthreads();
        if (tid < 50) {
            float pls = (t == 0) ? 0.f : logdelta;
            float mu = muv[tid], ls = lsv[tid], ep = eta[tid];
            float dm = mu - ep;
            red[tid] = (__expf(ls) + dm * dm) / (__expf(pls) + 1e-6f) - 1.f + pls - ls;
            g_etas[t * 50 + tid] = mu;
            eta[tid] = mu;
        }
        __syncthreads();
        if (tid == 0) {
            float s = 0.f;
            for (int i = 0; i < 50; i++) s += red[i];
            klacc += 0.5f * s;
        }
        __syncthreads();
    }
    if (tid == 0) g_scalars[2] = klacc;
}

// ---------------- build cat = [bows | eta_td] -------------------------------
__global__ void buildCatK(const float* __restrict__ bows, const int* __restrict__ times) {
    int stride = gridDim.x * blockDim.x;
    for (int i = blockIdx.x * blockDim.x + threadIdx.x; i < Dd * 3050; i += stride) {
        int d = i / 3050, j = i % 3050;
        g_cat[i] = (j < Vv) ? bows[d * Vv + j] : g_etas[times[d] * 50 + (j - Vv)];
    }
}

// ---------------- theta softmax + kl_theta ----------------------------------
__global__ void thetaKlK(const int* __restrict__ times) {
    int d = blockIdx.x, tid = threadIdx.x;
    __shared__ float sm[64];
    float mu = (tid < 50) ? g_muth[d * 50 + tid] : -1e30f;
    sm[tid] = mu; __syncthreads();
    for (int off = 32; off > 0; off >>= 1) {
        if (tid < off) sm[tid] = fmaxf(sm[tid], sm[tid + off]);
        __syncthreads();
    }
    float m = sm[0]; __syncthreads();
    float e = (tid < 50) ? __expf(mu - m) : 0.f;
    sm[tid] = e; __syncthreads();
    for (int off = 32; off > 0; off >>= 1) {
        if (tid < off) sm[tid] += sm[tid + off];
        __syncthreads();
    }
    float Z = sm[0]; __syncthreads();
    if (tid < 50) g_theta[d * 50 + tid] = e / Z;
    float term = 0.f;
    if (tid < 50) {
        float ls = g_lsth[d * 50 + tid];
        float et = g_etas[times[d] * 50 + tid];
        float dm = mu - et;
        term = (__expf(ls) + dm * dm) / (1.f + 1e-6f) - 1.f - ls;
    }
    sm[tid] = term; __syncthreads();
    for (int off = 32; off > 0; off >>= 1) {
        if (tid < off) sm[tid] += sm[tid + off];
        __syncthreads();
    }
    if (tid == 0) atomicAdd(&g_scalars[3], 0.5f * sm[0]);
}

// ---------------- lik + nll (bf16 P, 4 v per thread) ------------------------
__global__ void likNllK(const float* __restrict__ bows) {
    __shared__ float w[50];
    __shared__ float sm[256];
    int d = blockIdx.y, tid = threadIdx.x;
    if (tid < 50) w[tid] = g_theta[d * 50 + tid] / g_S[d * 50 + tid];
    __syncthreads();
    int v0 = (blockIdx.x * 256 + tid) * 4;
    float acc = 0.f;
    if (v0 < Vv) {
        const __nv_bfloat16* Pr = g_Pbf + (size_t)d * 50 * Vv + v0;
        float l0 = 0.f, l1 = 0.f, l2 = 0.f, l3 = 0.f;
#pragma unroll 10
        for (int k = 0; k < 50; k++) {
            uint2 u = *(const uint2*)&Pr[(size_t)k * Vv];
            __nv_bfloat162 pa = *(__nv_bfloat162*)&u.x;
            __nv_bfloat162 pb = *(__nv_bfloat162*)&u.y;
            float wk = w[k];
            l0 = fmaf(wk, __low2float(pa), l0);
            l1 = fmaf(wk, __high2float(pa), l1);
            l2 = fmaf(wk, __low2float(pb), l2);
            l3 = fmaf(wk, __high2float(pb), l3);
        }
        float4 bw = *(const float4*)&bows[(size_t)d * Vv + v0];
        acc = __logf(l0 + 1e-6f) * bw.x + __logf(l1 + 1e-6f) * bw.y
            + __logf(l2 + 1e-6f) * bw.z + __logf(l3 + 1e-6f) * bw.w;
    }
    float tot = blockReduceSum(acc, sm);
    if (tid == 0) atomicAdd(&g_scalars[0], tot);
}

__global__ void finalizeK(float* __restrict__ out) {
    if (threadIdx.x == 0) {
        out[0] = -g_scalars[0];
        out[1] = g_scalars[1];
        out[2] = g_scalars[2];
        out[3] = g_scalars[3];
    }
}

// ---------------- host orchestration ----------------------------------------
extern "C" void kernel_launch(void* const* d_in, const int* in_sizes, int n_in,
                              void* d_out, int out_size) {
    const float* bows    = (const float*)d_in[0];
    const float* rnn_inp = (const float*)d_in[1];
    const int*   times   = (const int*)d_in[2];
    const int*   sources = (const int*)d_in[3];
    const float* rho     = (const float*)d_in[4];
    const float* lam     = (const float*)d_in[5];
    const float* mu_q    = (const float*)d_in[6];
    const float* ls_q    = (const float*)d_in[7];
    const float* W_t1    = (const float*)d_in[8];
    const float* b_t1    = (const float*)d_in[9];
    const float* W_t2    = (const float*)d_in[10];
    const float* b_t2    = (const float*)d_in[11];
    const float* W_mu_th = (const float*)d_in[12];
    const float* b_mu_th = (const float*)d_in[13];
    const float* W_ls_th = (const float*)d_in[14];
    const float* b_ls_th = (const float*)d_in[15];
    const float* W_em    = (const float*)d_in[16];
    const float* b_em    = (const float*)d_in[17];
    const float* Wih0    = (const float*)d_in[18];
    const float* Whh0    = (const float*)d_in[19];
    const float* bl0     = (const float*)d_in[20];
    const float* Wih1    = (const float*)d_in[21];
    const float* Whh1    = (const float*)d_in[22];
    const float* bl1     = (const float*)d_in[23];
    const float* W_mu_e  = (const float*)d_in[24];
    const float* b_mu_e  = (const float*)d_in[25];
    const float* W_ls_e  = (const float*)d_in[26];
    const float* b_ls_e  = (const float*)d_in[27];

    float *pX, *pXw0, *pXw1, *pHs0, *pHs1, *pCat, *pH1, *pH2, *pMuth, *pLsth, *pS;
    float *pPm, *pPl;
    __nv_bfloat16 *pAbf, *pRhoBf, *pPbf;
    cudaGetSymbolAddress((void**)&pX, g_x);
    cudaGetSymbolAddress((void**)&pXw0, g_xw0);
    cudaGetSymbolAddress((void**)&pXw1, g_xw1);
    cudaGetSymbolAddress((void**)&pHs0, g_hs0);
    cudaGetSymbolAddress((void**)&pHs1, g_hs1);
    cudaGetSymbolAddress((void**)&pCat, g_cat);
    cudaGetSymbolAddress((void**)&pH1, g_h1);
    cudaGetSymbolAddress((void**)&pH2, g_h2);
    cudaGetSymbolAddress((void**)&pMuth, g_muth);
    cudaGetSymbolAddress((void**)&pLsth, g_lsth);
    cudaGetSymbolAddress((void**)&pS, g_S);
    cudaGetSymbolAddress((void**)&pPm, g_projMu);
    cudaGetSymbolAddress((void**)&pPl, g_projLs);
    cudaGetSymbolAddress((void**)&pAbf, g_Abf);
    cudaGetSymbolAddress((void**)&pRhoBf, g_rhoBf);
    cudaGetSymbolAddress((void**)&pPbf, g_Pbf);

    cudaFuncSetAttribute(gemmExpMMA, cudaFuncAttributeMaxDynamicSharedMemorySize, GEMM_SMEM);

    // 1-3: lstm deps; launch 4 = lstmK (ncu target: verify 101 -> ~40us)
    zeroAllK<<<256, 256>>>();
    gemmNN<<<dim3(4, 1, 1), 256>>>(rnn_inp, W_em, pX, 50, 200, 3000, 3000, b_em, 0);
    gemmNN<<<dim3(13, 1, 1), 256>>>(pX, Wih0, pXw0, 50, 800, 200, 200, bl0, 0);
    lstmK<<<4, 512>>>(pXw0, Whh0, pHs0);

    // big einsum path
    buildABfK<<<2048, 256>>>(mu_q, lam, times, sources);
    rhoBfK<<<512, 256>>>(rho);
    gemmExpMMA<<<dim3(24, 100), 256, GEMM_SMEM>>>(pAbf, pRhoBf, pPbf, pS);

    // LSTM layer 1
    gemmNN<<<dim3(13, 1, 1), 256>>>(pHs0, Wih1, pXw1, 50, 800, 200, 200, bl1, 0);
    lstmK<<<4, 512>>>(pXw1, Whh1, pHs1);

    // eta: parallel projections + short sequential scan
    gemmNN<<<dim3(1, 1, 1), 256>>>(pHs1, W_mu_e, pPm, 50, 50, 200, 200, b_mu_e, 0);
    gemmNN<<<dim3(1, 1, 1), 256>>>(pHs1, W_ls_e, pPl, 50, 50, 200, 200, b_ls_e, 0);
    etaScanK<<<1, 128>>>(pPm, pPl, W_mu_e, W_ls_e);

    klAlphaK<<<256, 256>>>(mu_q, ls_q);

    // theta MLP (split-K for parallelism; outputs pre-zeroed where z>1)
    buildCatK<<<1024, 256>>>(bows, times);
    gemmNN<<<dim3(13, 4, 4), 256>>>(pCat, W_t1, pH1, 256, 800, 3050, 768, nullptr, 0);
    biasActK<<<800, 256>>>(pH1, b_t1, 256, 800, 1);
    gemmNN<<<dim3(13, 4, 1), 256>>>(pH1, W_t2, pH2, 256, 800, 800, 800, b_t2, 1);
    gemmNN<<<dim3(1, 4, 8), 256>>>(pH2, W_mu_th, pMuth, 256, 50, 800, 112, nullptr, 0);
    biasActK<<<50, 256>>>(pMuth, b_mu_th, 256, 50, 0);
    gemmNN<<<dim3(1, 4, 8), 256>>>(pH2, W_ls_th, pLsth, 256, 50, 800, 112, nullptr, 0);
    biasActK<<<50, 256>>>(pLsth, b_ls_th, 256, 50, 0);
    thetaKlK<<<256, 64>>>(times);

    // lik/nll over bf16 P
    likNllK<<<dim3(3, 256), 256>>>(bows);

    finalizeK<<<1, 32>>>((float*)d_out);
}

// round 15
// speedup vs baseline: 1.3364x; 1.3364x over previous
#include <cuda_runtime.h>
#include <cuda_bf16.h>
#include <math.h>
#include <stdint.h>

#define Dd 256
#define Vv 3000
#define Tt 50
#define Kk 50
#define Ll 300
#define LPAD 320

// ---------------- scratch (__device__ globals; no allocations) --------------
static __device__ __align__(16) __nv_bfloat16 g_Pbf[12800 * 3000];   // exp(logits), bf16
static __device__ __align__(16) __nv_bfloat16 g_Abf[12800 * LPAD];
static __device__ __align__(16) __nv_bfloat16 g_rhoBf[3000 * LPAD];
static __device__ float g_S[12800];          // softmax denominators
static __device__ float g_x[50 * 200];
static __device__ float g_xw0[50 * 800];
static __device__ float g_xw1[50 * 800];
static __device__ float g_hs0[50 * 200];
static __device__ float g_hs1[50 * 200];
static __device__ float g_etas[50 * 50];
static __device__ float g_projMu[50 * 50];
static __device__ float g_projLs[50 * 50];
static __device__ float g_cat[256 * 3050];
static __device__ float g_h1[256 * 800];
static __device__ float g_h2[256 * 800];
static __device__ float g_muth[256 * 50];
static __device__ float g_lsth[256 * 50];
static __device__ float g_theta[256 * 50];
static __device__ float g_scalars[4];        // 0:+sum(log*bows) 1:kl_a 2:kl_eta 3:kl_th

// ---------------- fast exp on FMA pipe --------------------------------------
__device__ __forceinline__ float fexp_fast(float x) {
    float y = x * 1.4426950408889634f;
    float r = rintf(y);
    float f = y - r;
    float p = 1.3333558e-3f;
    p = fmaf(p, f, 9.6181291e-3f);
    p = fmaf(p, f, 5.5504109e-2f);
    p = fmaf(p, f, 2.4022651e-1f);
    p = fmaf(p, f, 6.9314718e-1f);
    p = fmaf(p, f, 1.0f);
    return p * __int_as_float(((int)r + 127) << 23);
}

__device__ __forceinline__ float blockReduceSum(float v, float* sm) {
    int tid = threadIdx.x;
    sm[tid] = v; __syncthreads();
    for (int off = blockDim.x >> 1; off > 0; off >>= 1) {
        if (tid < off) sm[tid] += sm[tid + off];
        __syncthreads();
    }
    return sm[0];
}

__device__ __forceinline__ void cp16(uint32_t dst, const void* src, int szok) {
    asm volatile("cp.async.cg.shared.global [%0], [%1], 16, %2;"
                 :: "r"(dst), "l"(src), "r"(szok) : "memory");
}

// ---------------- big GEMM on HMMA (mma.sync bf16) + exp epilogue -----------
#define BSTR 328
#define GEMM_SMEM (2 * 128 * BSTR * 2)

extern __shared__ __nv_bfloat16 dynsm[];

__global__ void __launch_bounds__(256, 1) gemmExpMMA(
    const __nv_bfloat16* __restrict__ Abf, const __nv_bfloat16* __restrict__ Bbf,
    __nv_bfloat16* __restrict__ Pbf, float* __restrict__ rowsum) {
    __nv_bfloat16* A_sm = dynsm;
    __nv_bfloat16* B_sm = dynsm + 128 * BSTR;

    const int tid = threadIdx.x;
    const int wid = tid >> 5, lane = tid & 31;
    const int warp_m = wid >> 2, warp_n = wid & 3;
    const int m_base = warp_m * 64, n_base = warp_n * 32;

    const int row0 = blockIdx.y * 128;
    const int col0 = blockIdx.x * 128;

    const uint32_t aBase = (uint32_t)__cvta_generic_to_shared(A_sm);
    const uint32_t bBase = (uint32_t)__cvta_generic_to_shared(B_sm);

    auto issue_chunk = [&](int c) {
#pragma unroll
        for (int it = 0; it < 5; it++) {
            int idx = tid + it * 256;
            int r = idx / 10, seg = idx - r * 10;
            uint32_t off = (uint32_t)((r * BSTR + c * 80 + seg * 8) * 2);
            cp16(aBase + off,
                 &Abf[(size_t)(row0 + r) * LPAD + c * 80 + seg * 8], 16);
            int n = col0 + r;
            cp16(bBase + off,
                 &Bbf[(size_t)(n < Vv ? n : Vv - 1) * LPAD + c * 80 + seg * 8],
                 n < Vv ? 16 : 0);
        }
        asm volatile("cp.async.commit_group;" ::: "memory");
    };

    issue_chunk(0);
    issue_chunk(1);

    float acc[4][4][4];
#pragma unroll
    for (int i = 0; i < 4; i++)
#pragma unroll
        for (int j = 0; j < 4; j++)
#pragma unroll
            for (int e = 0; e < 4; e++) acc[i][j][e] = 0.f;

#pragma unroll
    for (int c = 0; c < 4; c++) {
        if (c < 3) asm volatile("cp.async.wait_group 1;" ::: "memory");
        else       asm volatile("cp.async.wait_group 0;" ::: "memory");
        __syncthreads();
#pragma unroll
        for (int i = 0; i < 5; i++) {
            const int ks = c * 5 + i;
            uint32_t afr[4][4], bfr[4][2];
#pragma unroll
            for (int mi = 0; mi < 4; mi++) {
                uint32_t addr = aBase + (uint32_t)(((m_base + mi * 16 + (lane & 15)) * BSTR
                                 + ks * 16 + (lane >> 4) * 8) * 2);
                asm volatile(
                    "ldmatrix.sync.aligned.m8n8.x4.shared.b16 {%0,%1,%2,%3}, [%4];"
                    : "=r"(afr[mi][0]), "=r"(afr[mi][1]), "=r"(afr[mi][2]), "=r"(afr[mi][3])
                    : "r"(addr));
            }
#pragma unroll
            for (int ni = 0; ni < 4; ni++) {
                uint32_t addr = bBase + (uint32_t)(((n_base + ni * 8 + (lane & 7)) * BSTR
                                 + ks * 16 + ((lane >> 3) & 1) * 8) * 2);
                asm volatile(
                    "ldmatrix.sync.aligned.m8n8.x2.shared.b16 {%0,%1}, [%2];"
                    : "=r"(bfr[ni][0]), "=r"(bfr[ni][1])
                    : "r"(addr));
            }
#pragma unroll
            for (int mi = 0; mi < 4; mi++)
#pragma unroll
                for (int ni = 0; ni < 4; ni++) {
                    asm volatile(
                        "mma.sync.aligned.m16n8k16.row.col.f32.bf16.bf16.f32 "
                        "{%0,%1,%2,%3}, {%4,%5,%6,%7}, {%8,%9}, {%0,%1,%2,%3};"
                        : "+f"(acc[mi][ni][0]), "+f"(acc[mi][ni][1]),
                          "+f"(acc[mi][ni][2]), "+f"(acc[mi][ni][3])
                        : "r"(afr[mi][0]), "r"(afr[mi][1]), "r"(afr[mi][2]), "r"(afr[mi][3]),
                          "r"(bfr[ni][0]), "r"(bfr[ni][1]));
                }
        }
        if (c + 2 < 4) issue_chunk(c + 2);
    }

    const int g = lane >> 2, q = lane & 3;
#pragma unroll
    for (int mi = 0; mi < 4; mi++) {
        float rsLo = 0.f, rsHi = 0.f;
        int rLo = row0 + m_base + mi * 16 + g;
#pragma unroll
        for (int ni = 0; ni < 4; ni++) {
            int col = col0 + n_base + ni * 8 + q * 2;
            if (col < Vv) {
                __nv_bfloat162 bLo = __floats2bfloat162_rn(
                    fexp_fast(acc[mi][ni][0]), fexp_fast(acc[mi][ni][1]));
                __nv_bfloat162 bHi = __floats2bfloat162_rn(
                    fexp_fast(acc[mi][ni][2]), fexp_fast(acc[mi][ni][3]));
                rsLo += __low2float(bLo) + __high2float(bLo);
                rsHi += __low2float(bHi) + __high2float(bHi);
                *(__nv_bfloat162*)&Pbf[(size_t)rLo * Vv + col] = bLo;
                *(__nv_bfloat162*)&Pbf[(size_t)(rLo + 8) * Vv + col] = bHi;
            }
        }
        rsLo += __shfl_xor_sync(0xffffffffu, rsLo, 1);
        rsLo += __shfl_xor_sync(0xffffffffu, rsLo, 2);
        rsHi += __shfl_xor_sync(0xffffffffu, rsHi, 1);
        rsHi += __shfl_xor_sync(0xffffffffu, rsHi, 2);
        if (q == 0) {
            atomicAdd(&rowsum[rLo], rsLo);
            atomicAdd(&rowsum[rLo + 8], rsHi);
        }
    }
}

// ---------------- build bf16 operands ---------------------------------------
__global__ void buildABfK(const float* __restrict__ alpha, const float* __restrict__ lam,
                          const int* __restrict__ times, const int* __restrict__ sources) {
    int stride = gridDim.x * blockDim.x;
    for (int i = blockIdx.x * blockDim.x + threadIdx.x; i < 12800 * LPAD; i += stride) {
        int r = i / LPAD, l = i - r * LPAD;
        int d = r / Kk, k = r - d * Kk;
        float v = 0.f;
        if (l < Ll)
            v = alpha[((size_t)k * Tt + times[d]) * Ll + l] * lam[(size_t)sources[d] * Ll + l];
        g_Abf[i] = __float2bfloat16(v);
    }
}

__global__ void rhoBfK(const float* __restrict__ rho) {
    int stride = gridDim.x * blockDim.x;
    for (int i = blockIdx.x * blockDim.x + threadIdx.x; i < Vv * LPAD; i += stride) {
        int r = i / LPAD, l = i - r * LPAD;
        g_rhoBf[i] = __float2bfloat16(l < Ll ? rho[(size_t)r * Ll + l] : 0.f);
    }
}

// ---------------- zero scratch (split-K outputs + accumulators) -------------
__global__ void zeroAllK() {
    int stride = gridDim.x * blockDim.x;
    for (int i = blockIdx.x * blockDim.x + threadIdx.x; i < 204800; i += stride) {
        g_h1[i] = 0.f;
        if (i < 12800) { g_S[i] = 0.f; g_muth[i] = 0.f; g_lsth[i] = 0.f; }
        if (i < 10000) g_x[i] = 0.f;
        if (i < 4) g_scalars[i] = 0.f;
    }
}

// ---------------- kl_alpha --------------------------------------------------
__global__ void klAlphaK(const float* __restrict__ mu, const float* __restrict__ ls) {
    __shared__ float sm[256];
    const float logdelta = logf(0.005f);
    const float invdel = 1.f / (__expf(logdelta) + 1e-6f);
    int stride = gridDim.x * blockDim.x;
    float acc = 0.f;
    for (int i = blockIdx.x * blockDim.x + threadIdx.x; i < Kk * Tt * Ll; i += stride) {
        int t = (i / Ll) % Tt;
        float qm = mu[i], ql = ls[i];
        if (t == 0) {
            acc += (__expf(ql) + qm * qm) / (1.f + 1e-6f) - 1.f - ql;
        } else {
            float pm = mu[i - Ll];
            float d = qm - pm;
            acc += (__expf(ql) + d * d) * invdel - 1.f + logdelta - ql;
        }
    }
    float tot = blockReduceSum(acc, sm);
    if (threadIdx.x == 0) atomicAdd(&g_scalars[1], 0.5f * tot);
}

// ---------------- generic tiled GEMM (NN, split-K atomic, opt fused bias) ---
__global__ void gemmNN(const float* __restrict__ A, const float* __restrict__ B,
                       float* __restrict__ C, int M, int N, int Kd, int kchunk,
                       const float* __restrict__ bias, int relu) {
    __shared__ float As[16][64];
    __shared__ float Bs[16][64];
    int tid = threadIdx.x;
    int tx = tid & 15, ty = tid >> 4;
    int row0 = blockIdx.y * 64, col0 = blockIdx.x * 64;
    int kbeg = blockIdx.z * kchunk;
    int kend = min(Kd, kbeg + kchunk);
    int aRow = tid >> 2, aCol = (tid & 3) << 2;
    int bRow = tid >> 4, bCol = (tid & 15) << 2;
    float acc[4][4] = {};
    for (int k0 = kbeg; k0 < kend; k0 += 16) {
#pragma unroll
        for (int i = 0; i < 4; i++) {
            int kk = k0 + aCol + i, r = row0 + aRow;
            As[aCol + i][aRow] = (r < M && kk < kend) ? A[(size_t)r * Kd + kk] : 0.f;
        }
#pragma unroll
        for (int i = 0; i < 4; i++) {
            int kk = k0 + bRow, n = col0 + bCol + i;
            Bs[bRow][bCol + i] = (n < N && kk < kend) ? B[(size_t)kk * N + n] : 0.f;
        }
        __syncthreads();
#pragma unroll
        for (int kk = 0; kk < 16; kk++) {
            float a[4], b[4];
#pragma unroll
            for (int i = 0; i < 4; i++) a[i] = As[kk][ty * 4 + i];
#pragma unroll
            for (int j = 0; j < 4; j++) b[j] = Bs[kk][tx * 4 + j];
#pragma unroll
            for (int i = 0; i < 4; i++)
#pragma unroll
                for (int j = 0; j < 4; j++) acc[i][j] = fmaf(a[i], b[j], acc[i][j]);
        }
        __syncthreads();
    }
#pragma unroll
    for (int i = 0; i < 4; i++) {
        int r = row0 + ty * 4 + i;
        if (r >= M) continue;
#pragma unroll
        for (int j = 0; j < 4; j++) {
            int c = col0 + tx * 4 + j;
            if (c >= N) continue;
            if (gridDim.z > 1) atomicAdd(&C[(size_t)r * N + c], acc[i][j]);
            else {
                float v = acc[i][j];
                if (bias) v += bias[c];
                if (relu) v = fmaxf(v, 0.f);
                C[(size_t)r * N + c] = v;
            }
        }
    }
}

// ---------------- bias (+optional relu) -------------------------------------
__global__ void biasActK(float* __restrict__ C, const float* __restrict__ b,
                         int M, int N, int relu) {
    int stride = gridDim.x * blockDim.x;
    for (int i = blockIdx.x * blockDim.x + threadIdx.x; i < M * N; i += stride) {
        float v = C[i] + b[i % N];
        if (relu) v = fmaxf(v, 0.f);
        C[i] = v;
    }
}

// ---------------- LSTM: reg Whh (bf16x2) + smem xw + fast activations -------
__device__ __forceinline__ unsigned ctarank_() {
    unsigned r; asm("mov.u32 %0, %%cluster_ctarank;" : "=r"(r)); return r;
}
__device__ __forceinline__ void cluster_sync_() {
    asm volatile("barrier.cluster.arrive.aligned;" ::: "memory");
    asm volatile("barrier.cluster.wait.aligned;" ::: "memory");
}
__device__ __forceinline__ float sigmoid_fast(float x) {
    return __fdividef(1.f, 1.f + __expf(-x));
}
__device__ __forceinline__ float tanh_fast(float x) {
    return __fdividef(2.f, 1.f + __expf(-2.f * x)) - 1.f;
}

__global__ void __launch_bounds__(512, 1) __cluster_dims__(4, 1, 1)
lstmK(const float* __restrict__ xw, const float* __restrict__ Whh,
      float* __restrict__ hs) {
    __shared__ float xws[10000];               // this CTA's 50x200 xw slice (40KB)
    __shared__ __align__(16) float hA[256];
    __shared__ __align__(16) float hB[256];
    __shared__ float pbuf[512];
    int tid = threadIdx.x;
    unsigned rank = ctarank_();

    int j = tid % 200;
    int half = (tid < 400) ? (tid / 200) : 0;
    int col = (j / 50) * 200 + (int)rank * 50 + (j % 50);

    uint32_t w2[50];
    if (tid < 400) {
#pragma unroll
        for (int i = 0; i < 50; i++) {
            float f0 = Whh[(size_t)(half * 100 + 2 * i) * 800 + col];
            float f1 = Whh[(size_t)(half * 100 + 2 * i + 1) * 800 + col];
            __nv_bfloat162 b2 = __floats2bfloat162_rn(f0, f1);
            w2[i] = *(uint32_t*)&b2;
        }
    }
    for (int idx = tid; idx < 10000; idx += 512) {
        int t = idx / 200, jl = idx - t * 200;
        int cj = (jl / 50) * 200 + (int)rank * 50 + (jl % 50);
        xws[idx] = xw[t * 800 + cj];
    }
    if (tid < 200) hA[tid] = 0.f;
    float c = 0.f;
    __syncthreads();
    cluster_sync_();

    const uint32_t hAaddr = (uint32_t)__cvta_generic_to_shared(hA);
    const uint32_t hBaddr = (uint32_t)__cvta_generic_to_shared(hB);

    for (int t = 0; t < Tt; t++) {
        const float4* hv4 = (const float4*)((t & 1) ? hB : hA);
        const uint32_t hwaddr = (t & 1) ? hAaddr : hBaddr;
        if (tid < 400) {
            float p0 = 0.f, p1 = 0.f;
            const float4* hh4 = hv4 + half * 25;
#pragma unroll
            for (int i = 0; i < 25; i++) {
                float4 hh = hh4[i];
                uint32_t wa = w2[2 * i], wb = w2[2 * i + 1];
                p0 = fmaf(hh.x, __int_as_float(wa << 16), p0);
                p1 = fmaf(hh.y, __int_as_float(wa & 0xffff0000u), p1);
                p0 = fmaf(hh.z, __int_as_float(wb << 16), p0);
                p1 = fmaf(hh.w, __int_as_float(wb & 0xffff0000u), p1);
            }
            pbuf[tid] = p0 + p1;
        }
        __syncthreads();
        if (tid < 50) {
            int base = t * 200;
            float gi = xws[base + tid]       + pbuf[tid]       + pbuf[tid + 200];
            float gf = xws[base + 50 + tid]  + pbuf[50 + tid]  + pbuf[250 + tid];
            float gg = xws[base + 100 + tid] + pbuf[100 + tid] + pbuf[300 + tid];
            float go = xws[base + 150 + tid] + pbuf[150 + tid] + pbuf[350 + tid];
            c = sigmoid_fast(gf) * c + sigmoid_fast(gi) * tanh_fast(gg);
            float h2 = sigmoid_fast(go) * tanh_fast(c);
            int e = (int)rank * 50 + tid;
            hs[t * 200 + e] = h2;
            uint32_t la = hwaddr + (uint32_t)(e * 4);
#pragma unroll
            for (unsigned r2 = 0; r2 < 4; r2++) {
                uint32_t ra;
                asm volatile("mapa.shared::cluster.u32 %0, %1, %2;"
                             : "=r"(ra) : "r"(la), "r"(r2));
                asm volatile("st.shared::cluster.f32 [%0], %1;"
                             :: "r"(ra), "f"(h2) : "memory");
            }
        }
        cluster_sync_();
    }
}

// ---------------- eta scan: only the 50x50 recurrence is sequential ---------
__global__ void etaScanK(const float* __restrict__ projMu, const float* __restrict__ projLs,
                         const float* __restrict__ Wmu, const float* __restrict__ Wls) {
    __shared__ float sWm[2500], sWl[2500];
    __shared__ float eta[50], muv[50], lsv[50], red[50];
    __shared__ float klacc;
    int tid = threadIdx.x;   // 128
    for (int i = tid; i < 2500; i += 128) {
        sWm[i] = Wmu[10000 + i];
        sWl[i] = Wls[10000 + i];
    }
    if (tid < 50) eta[tid] = 0.f;
    if (tid == 0) klacc = 0.f;
    const float logdelta = logf(0.005f);
    __syncthreads();
    for (int t = 0; t < Tt; t++) {
        if (tid < 50) {
            float m = projMu[t * 50 + tid];
#pragma unroll 10
            for (int jj = 0; jj < 50; jj++) m = fmaf(eta[jj], sWm[jj * 50 + tid], m);
            muv[tid] = m;
        } else if (tid >= 64 && tid < 114) {
            int k = tid - 64;
            float m = projLs[t * 50 + k];
#pragma unroll 10
            for (int jj = 0; jj < 50; jj++) m = fmaf(eta[jj], sWl[jj * 50 + k], m);
            lsv[k] = m;
        }
        __syncthreads();
        if (tid < 50) {
            float pls = (t == 0) ? 0.f : logdelta;
            float mu = muv[tid], ls = lsv[tid], ep = eta[tid];
            float dm = mu - ep;
            red[tid] = (__expf(ls) + dm * dm) / (__expf(pls) + 1e-6f) - 1.f + pls - ls;
            g_etas[t * 50 + tid] = mu;
            eta[tid] = mu;
        }
        __syncthreads();
        if (tid == 0) {
            float s = 0.f;
            for (int i = 0; i < 50; i++) s += red[i];
            klacc += 0.5f * s;
        }
        __syncthreads();
    }
    if (tid == 0) g_scalars[2] = klacc;
}

// ---------------- build cat = [bows | eta_td] -------------------------------
__global__ void buildCatK(const float* __restrict__ bows, const int* __restrict__ times) {
    int stride = gridDim.x * blockDim.x;
    for (int i = blockIdx.x * blockDim.x + threadIdx.x; i < Dd * 3050; i += stride) {
        int d = i / 3050, j = i % 3050;
        g_cat[i] = (j < Vv) ? bows[d * Vv + j] : g_etas[times[d] * 50 + (j - Vv)];
    }
}

// ---------------- theta softmax + kl_theta ----------------------------------
__global__ void thetaKlK(const int* __restrict__ times) {
    int d = blockIdx.x, tid = threadIdx.x;
    __shared__ float sm[64];
    float mu = (tid < 50) ? g_muth[d * 50 + tid] : -1e30f;
    sm[tid] = mu; __syncthreads();
    for (int off = 32; off > 0; off >>= 1) {
        if (tid < off) sm[tid] = fmaxf(sm[tid], sm[tid + off]);
        __syncthreads();
    }
    float m = sm[0]; __syncthreads();
    float e = (tid < 50) ? __expf(mu - m) : 0.f;
    sm[tid] = e; __syncthreads();
    for (int off = 32; off > 0; off >>= 1) {
        if (tid < off) sm[tid] += sm[tid + off];
        __syncthreads();
    }
    float Z = sm[0]; __syncthreads();
    if (tid < 50) g_theta[d * 50 + tid] = e / Z;
    float term = 0.f;
    if (tid < 50) {
        float ls = g_lsth[d * 50 + tid];
        float et = g_etas[times[d] * 50 + tid];
        float dm = mu - et;
        term = (__expf(ls) + dm * dm) / (1.f + 1e-6f) - 1.f - ls;
    }
    sm[tid] = term; __syncthreads();
    for (int off = 32; off > 0; off >>= 1) {
        if (tid < off) sm[tid] += sm[tid + off];
        __syncthreads();
    }
    if (tid == 0) atomicAdd(&g_scalars[3], 0.5f * sm[0]);
}

// ---------------- lik + nll (bf16 P, 4 v per thread) ------------------------
__global__ void likNllK(const float* __restrict__ bows) {
    __shared__ float w[50];
    __shared__ float sm[256];
    int d = blockIdx.y, tid = threadIdx.x;
    if (tid < 50) w[tid] = g_theta[d * 50 + tid] / g_S[d * 50 + tid];
    __syncthreads();
    int v0 = (blockIdx.x * 256 + tid) * 4;
    float acc = 0.f;
    if (v0 < Vv) {
        const __nv_bfloat16* Pr = g_Pbf + (size_t)d * 50 * Vv + v0;
        float l0 = 0.f, l1 = 0.f, l2 = 0.f, l3 = 0.f;
#pragma unroll 10
        for (int k = 0; k < 50; k++) {
            uint2 u = *(const uint2*)&Pr[(size_t)k * Vv];
            __nv_bfloat162 pa = *(__nv_bfloat162*)&u.x;
            __nv_bfloat162 pb = *(__nv_bfloat162*)&u.y;
            float wk = w[k];
            l0 = fmaf(wk, __low2float(pa), l0);
            l1 = fmaf(wk, __high2float(pa), l1);
            l2 = fmaf(wk, __low2float(pb), l2);
            l3 = fmaf(wk, __high2float(pb), l3);
        }
        float4 bw = *(const float4*)&bows[(size_t)d * Vv + v0];
        acc = __logf(l0 + 1e-6f) * bw.x + __logf(l1 + 1e-6f) * bw.y
            + __logf(l2 + 1e-6f) * bw.z + __logf(l3 + 1e-6f) * bw.w;
    }
    float tot = blockReduceSum(acc, sm);
    if (tid == 0) atomicAdd(&g_scalars[0], tot);
}

__global__ void finalizeK(float* __restrict__ out) {
    if (threadIdx.x == 0) {
        out[0] = -g_scalars[0];
        out[1] = g_scalars[1];
        out[2] = g_scalars[2];
        out[3] = g_scalars[3];
    }
}

// ---------------- host orchestration (R12 ordering restored) ----------------
extern "C" void kernel_launch(void* const* d_in, const int* in_sizes, int n_in,
                              void* d_out, int out_size) {
    const float* bows    = (const float*)d_in[0];
    const float* rnn_inp = (const float*)d_in[1];
    const int*   times   = (const int*)d_in[2];
    const int*   sources = (const int*)d_in[3];
    const float* rho     = (const float*)d_in[4];
    const float* lam     = (const float*)d_in[5];
    const float* mu_q    = (const float*)d_in[6];
    const float* ls_q    = (const float*)d_in[7];
    const float* W_t1    = (const float*)d_in[8];
    const float* b_t1    = (const float*)d_in[9];
    const float* W_t2    = (const float*)d_in[10];
    const float* b_t2    = (const float*)d_in[11];
    const float* W_mu_th = (const float*)d_in[12];
    const float* b_mu_th = (const float*)d_in[13];
    const float* W_ls_th = (const float*)d_in[14];
    const float* b_ls_th = (const float*)d_in[15];
    const float* W_em    = (const float*)d_in[16];
    const float* b_em    = (const float*)d_in[17];
    const float* Wih0    = (const float*)d_in[18];
    const float* Whh0    = (const float*)d_in[19];
    const float* bl0     = (const float*)d_in[20];
    const float* Wih1    = (const float*)d_in[21];
    const float* Whh1    = (const float*)d_in[22];
    const float* bl1     = (const float*)d_in[23];
    const float* W_mu_e  = (const float*)d_in[24];
    const float* b_mu_e  = (const float*)d_in[25];
    const float* W_ls_e  = (const float*)d_in[26];
    const float* b_ls_e  = (const float*)d_in[27];

    float *pX, *pXw0, *pXw1, *pHs0, *pHs1, *pCat, *pH1, *pH2, *pMuth, *pLsth, *pS;
    float *pPm, *pPl;
    __nv_bfloat16 *pAbf, *pRhoBf, *pPbf;
    cudaGetSymbolAddress((void**)&pX, g_x);
    cudaGetSymbolAddress((void**)&pXw0, g_xw0);
    cudaGetSymbolAddress((void**)&pXw1, g_xw1);
    cudaGetSymbolAddress((void**)&pHs0, g_hs0);
    cudaGetSymbolAddress((void**)&pHs1, g_hs1);
    cudaGetSymbolAddress((void**)&pCat, g_cat);
    cudaGetSymbolAddress((void**)&pH1, g_h1);
    cudaGetSymbolAddress((void**)&pH2, g_h2);
    cudaGetSymbolAddress((void**)&pMuth, g_muth);
    cudaGetSymbolAddress((void**)&pLsth, g_lsth);
    cudaGetSymbolAddress((void**)&pS, g_S);
    cudaGetSymbolAddress((void**)&pPm, g_projMu);
    cudaGetSymbolAddress((void**)&pPl, g_projLs);
    cudaGetSymbolAddress((void**)&pAbf, g_Abf);
    cudaGetSymbolAddress((void**)&pRhoBf, g_rhoBf);
    cudaGetSymbolAddress((void**)&pPbf, g_Pbf);

    cudaFuncSetAttribute(gemmExpMMA, cudaFuncAttributeMaxDynamicSharedMemorySize, GEMM_SMEM);

    // 1-3: gemmExp deps; launch 4 = gemmExpMMA (known-120us control)
    zeroAllK<<<256, 256>>>();
    buildABfK<<<2048, 256>>>(mu_q, lam, times, sources);
    rhoBfK<<<512, 256>>>(rho);
    gemmExpMMA<<<dim3(24, 100), 256, GEMM_SMEM>>>(pAbf, pRhoBf, pPbf, pS);

    klAlphaK<<<256, 256>>>(mu_q, ls_q);

    // x = rnn_inp @ W_em + b_em  (split-K z=8 for parallelism)
    gemmNN<<<dim3(4, 1, 8), 256>>>(rnn_inp, W_em, pX, 50, 200, 3000, 384, nullptr, 0);
    biasActK<<<40, 256>>>(pX, b_em, 50, 200, 0);

    // LSTM layer 0 (bias fused into xw gemm)
    gemmNN<<<dim3(13, 1, 1), 256>>>(pX, Wih0, pXw0, 50, 800, 200, 200, bl0, 0);
    lstmK<<<4, 512>>>(pXw0, Whh0, pHs0);

    // LSTM layer 1
    gemmNN<<<dim3(13, 1, 1), 256>>>(pHs0, Wih1, pXw1, 50, 800, 200, 200, bl1, 0);
    lstmK<<<4, 512>>>(pXw1, Whh1, pHs1);

    // eta: parallel projections + short sequential scan
    gemmNN<<<dim3(1, 1, 1), 256>>>(pHs1, W_mu_e, pPm, 50, 50, 200, 200, b_mu_e, 0);
    gemmNN<<<dim3(1, 1, 1), 256>>>(pHs1, W_ls_e, pPl, 50, 50, 200, 200, b_ls_e, 0);
    etaScanK<<<1, 128>>>(pPm, pPl, W_mu_e, W_ls_e);

    // theta MLP (split-K restored for parallelism; outputs pre-zeroed)
    buildCatK<<<1024, 256>>>(bows, times);
    gemmNN<<<dim3(13, 4, 4), 256>>>(pCat, W_t1, pH1, 256, 800, 3050, 768, nullptr, 0);
    biasActK<<<800, 256>>>(pH1, b_t1, 256, 800, 1);
    gemmNN<<<dim3(13, 4, 1), 256>>>(pH1, W_t2, pH2, 256, 800, 800, 800, b_t2, 1);
    gemmNN<<<dim3(1, 4, 8), 256>>>(pH2, W_mu_th, pMuth, 256, 50, 800, 112, nullptr, 0);
    biasActK<<<50, 256>>>(pMuth, b_mu_th, 256, 50, 0);
    gemmNN<<<dim3(1, 4, 8), 256>>>(pH2, W_ls_th, pLsth, 256, 50, 800, 112, nullptr, 0);
    biasActK<<<50, 256>>>(pLsth, b_ls_th, 256, 50, 0);
    thetaKlK<<<256, 64>>>(times);

    // lik/nll over bf16 P
    likNllK<<<dim3(3, 256), 256>>>(bows);

    finalizeK<<<1, 32>>>((float*)d_out);
}

// round 16
// speedup vs baseline: 1.4286x; 1.0690x over previous
#include <cuda_runtime.h>
#include <cuda_bf16.h>
#include <math.h>
#include <stdint.h>

#define Dd 256
#define Vv 3000
#define Tt 50
#define Kk 50
#define Ll 300
#define LPAD 320

// ---------------- scratch (__device__ globals; no allocations) --------------
static __device__ __align__(16) __nv_bfloat16 g_Pbf[12800 * 3000];   // exp(logits), bf16
static __device__ __align__(16) __nv_bfloat16 g_Abf[12800 * LPAD];
static __device__ __align__(16) __nv_bfloat16 g_rhoBf[3000 * LPAD];
static __device__ float g_S[12800];          // softmax denominators
static __device__ float g_x[50 * 200];
static __device__ float g_xw0[50 * 800];
static __device__ float g_xw1[50 * 800];
static __device__ float g_hs0[50 * 200];
static __device__ float g_hs1[50 * 200];
static __device__ float g_etas[50 * 50];
static __device__ float g_projMu[50 * 50];
static __device__ float g_projLs[50 * 50];
static __device__ float g_cat[256 * 3050];
static __device__ float g_h1[256 * 800];
static __device__ float g_h2[256 * 800];
static __device__ float g_muth[256 * 50];
static __device__ float g_lsth[256 * 50];
static __device__ float g_theta[256 * 50];
static __device__ float g_scalars[4];        // 0:+sum(log*bows) 1:kl_a 2:kl_eta 3:kl_th

// ---------------- fast exp on FMA pipe --------------------------------------
__device__ __forceinline__ float fexp_fast(float x) {
    float y = x * 1.4426950408889634f;
    float r = rintf(y);
    float f = y - r;
    float p = 1.3333558e-3f;
    p = fmaf(p, f, 9.6181291e-3f);
    p = fmaf(p, f, 5.5504109e-2f);
    p = fmaf(p, f, 2.4022651e-1f);
    p = fmaf(p, f, 6.9314718e-1f);
    p = fmaf(p, f, 1.0f);
    return p * __int_as_float(((int)r + 127) << 23);
}

__device__ __forceinline__ float blockReduceSum(float v, float* sm) {
    int tid = threadIdx.x;
    sm[tid] = v; __syncthreads();
    for (int off = blockDim.x >> 1; off > 0; off >>= 1) {
        if (tid < off) sm[tid] += sm[tid + off];
        __syncthreads();
    }
    return sm[0];
}

__device__ __forceinline__ void cp16(uint32_t dst, const void* src, int szok) {
    asm volatile("cp.async.cg.shared.global [%0], [%1], 16, %2;"
                 :: "r"(dst), "l"(src), "r"(szok) : "memory");
}

// ---------------- big GEMM on HMMA (mma.sync bf16) + exp epilogue -----------
#define BSTR 328
#define GEMM_SMEM (2 * 128 * BSTR * 2)

extern __shared__ __nv_bfloat16 dynsm[];

__global__ void __launch_bounds__(256, 1) gemmExpMMA(
    const __nv_bfloat16* __restrict__ Abf, const __nv_bfloat16* __restrict__ Bbf,
    __nv_bfloat16* __restrict__ Pbf, float* __restrict__ rowsum) {
    __nv_bfloat16* A_sm = dynsm;
    __nv_bfloat16* B_sm = dynsm + 128 * BSTR;

    const int tid = threadIdx.x;
    const int wid = tid >> 5, lane = tid & 31;
    const int warp_m = wid >> 2, warp_n = wid & 3;
    const int m_base = warp_m * 64, n_base = warp_n * 32;

    const int row0 = blockIdx.y * 128;
    const int col0 = blockIdx.x * 128;

    const uint32_t aBase = (uint32_t)__cvta_generic_to_shared(A_sm);
    const uint32_t bBase = (uint32_t)__cvta_generic_to_shared(B_sm);

    auto issue_chunk = [&](int c) {
#pragma unroll
        for (int it = 0; it < 5; it++) {
            int idx = tid + it * 256;
            int r = idx / 10, seg = idx - r * 10;
            uint32_t off = (uint32_t)((r * BSTR + c * 80 + seg * 8) * 2);
            cp16(aBase + off,
                 &Abf[(size_t)(row0 + r) * LPAD + c * 80 + seg * 8], 16);
            int n = col0 + r;
            cp16(bBase + off,
                 &Bbf[(size_t)(n < Vv ? n : Vv - 1) * LPAD + c * 80 + seg * 8],
                 n < Vv ? 16 : 0);
        }
        asm volatile("cp.async.commit_group;" ::: "memory");
    };

    issue_chunk(0);
    issue_chunk(1);

    float acc[4][4][4];
#pragma unroll
    for (int i = 0; i < 4; i++)
#pragma unroll
        for (int j = 0; j < 4; j++)
#pragma unroll
            for (int e = 0; e < 4; e++) acc[i][j][e] = 0.f;

#pragma unroll
    for (int c = 0; c < 4; c++) {
        if (c < 3) asm volatile("cp.async.wait_group 1;" ::: "memory");
        else       asm volatile("cp.async.wait_group 0;" ::: "memory");
        __syncthreads();
#pragma unroll
        for (int i = 0; i < 5; i++) {
            const int ks = c * 5 + i;
            uint32_t afr[4][4], bfr[4][2];
#pragma unroll
            for (int mi = 0; mi < 4; mi++) {
                uint32_t addr = aBase + (uint32_t)(((m_base + mi * 16 + (lane & 15)) * BSTR
                                 + ks * 16 + (lane >> 4) * 8) * 2);
                asm volatile(
                    "ldmatrix.sync.aligned.m8n8.x4.shared.b16 {%0,%1,%2,%3}, [%4];"
                    : "=r"(afr[mi][0]), "=r"(afr[mi][1]), "=r"(afr[mi][2]), "=r"(afr[mi][3])
                    : "r"(addr));
            }
#pragma unroll
            for (int ni = 0; ni < 4; ni++) {
                uint32_t addr = bBase + (uint32_t)(((n_base + ni * 8 + (lane & 7)) * BSTR
                                 + ks * 16 + ((lane >> 3) & 1) * 8) * 2);
                asm volatile(
                    "ldmatrix.sync.aligned.m8n8.x2.shared.b16 {%0,%1}, [%2];"
                    : "=r"(bfr[ni][0]), "=r"(bfr[ni][1])
                    : "r"(addr));
            }
#pragma unroll
            for (int mi = 0; mi < 4; mi++)
#pragma unroll
                for (int ni = 0; ni < 4; ni++) {
                    asm volatile(
                        "mma.sync.aligned.m16n8k16.row.col.f32.bf16.bf16.f32 "
                        "{%0,%1,%2,%3}, {%4,%5,%6,%7}, {%8,%9}, {%0,%1,%2,%3};"
                        : "+f"(acc[mi][ni][0]), "+f"(acc[mi][ni][1]),
                          "+f"(acc[mi][ni][2]), "+f"(acc[mi][ni][3])
                        : "r"(afr[mi][0]), "r"(afr[mi][1]), "r"(afr[mi][2]), "r"(afr[mi][3]),
                          "r"(bfr[ni][0]), "r"(bfr[ni][1]));
                }
        }
        if (c + 2 < 4) issue_chunk(c + 2);
    }

    const int g = lane >> 2, q = lane & 3;
#pragma unroll
    for (int mi = 0; mi < 4; mi++) {
        float rsLo = 0.f, rsHi = 0.f;
        int rLo = row0 + m_base + mi * 16 + g;
#pragma unroll
        for (int ni = 0; ni < 4; ni++) {
            int col = col0 + n_base + ni * 8 + q * 2;
            if (col < Vv) {
                __nv_bfloat162 bLo = __floats2bfloat162_rn(
                    fexp_fast(acc[mi][ni][0]), fexp_fast(acc[mi][ni][1]));
                __nv_bfloat162 bHi = __floats2bfloat162_rn(
                    fexp_fast(acc[mi][ni][2]), fexp_fast(acc[mi][ni][3]));
                rsLo += __low2float(bLo) + __high2float(bLo);
                rsHi += __low2float(bHi) + __high2float(bHi);
                *(__nv_bfloat162*)&Pbf[(size_t)rLo * Vv + col] = bLo;
                *(__nv_bfloat162*)&Pbf[(size_t)(rLo + 8) * Vv + col] = bHi;
            }
        }
        rsLo += __shfl_xor_sync(0xffffffffu, rsLo, 1);
        rsLo += __shfl_xor_sync(0xffffffffu, rsLo, 2);
        rsHi += __shfl_xor_sync(0xffffffffu, rsHi, 1);
        rsHi += __shfl_xor_sync(0xffffffffu, rsHi, 2);
        if (q == 0) {
            atomicAdd(&rowsum[rLo], rsLo);
            atomicAdd(&rowsum[rLo + 8], rsHi);
        }
    }
}

// ---------------- build bf16 operands ---------------------------------------
__global__ void buildABfK(const float* __restrict__ alpha, const float* __restrict__ lam,
                          const int* __restrict__ times, const int* __restrict__ sources) {
    int stride = gridDim.x * blockDim.x;
    for (int i = blockIdx.x * blockDim.x + threadIdx.x; i < 12800 * LPAD; i += stride) {
        int r = i / LPAD, l = i - r * LPAD;
        int d = r / Kk, k = r - d * Kk;
        float v = 0.f;
        if (l < Ll)
            v = alpha[((size_t)k * Tt + times[d]) * Ll + l] * lam[(size_t)sources[d] * Ll + l];
        g_Abf[i] = __float2bfloat16(v);
    }
}

__global__ void rhoBfK(const float* __restrict__ rho) {
    int stride = gridDim.x * blockDim.x;
    for (int i = blockIdx.x * blockDim.x + threadIdx.x; i < Vv * LPAD; i += stride) {
        int r = i / LPAD, l = i - r * LPAD;
        g_rhoBf[i] = __float2bfloat16(l < Ll ? rho[(size_t)r * Ll + l] : 0.f);
    }
}

// ---------------- zero scratch (split-K outputs + accumulators) -------------
__global__ void zeroAllK() {
    int stride = gridDim.x * blockDim.x;
    for (int i = blockIdx.x * blockDim.x + threadIdx.x; i < 204800; i += stride) {
        g_h1[i] = 0.f;
        if (i < 12800) { g_S[i] = 0.f; g_muth[i] = 0.f; g_lsth[i] = 0.f; }
        if (i < 10000) g_x[i] = 0.f;
        if (i < 4) g_scalars[i] = 0.f;
    }
}

// ---------------- kl_alpha --------------------------------------------------
__global__ void klAlphaK(const float* __restrict__ mu, const float* __restrict__ ls) {
    __shared__ float sm[256];
    const float logdelta = logf(0.005f);
    const float invdel = 1.f / (__expf(logdelta) + 1e-6f);
    int stride = gridDim.x * blockDim.x;
    float acc = 0.f;
    for (int i = blockIdx.x * blockDim.x + threadIdx.x; i < Kk * Tt * Ll; i += stride) {
        int t = (i / Ll) % Tt;
        float qm = mu[i], ql = ls[i];
        if (t == 0) {
            acc += (__expf(ql) + qm * qm) / (1.f + 1e-6f) - 1.f - ql;
        } else {
            float pm = mu[i - Ll];
            float d = qm - pm;
            acc += (__expf(ql) + d * d) * invdel - 1.f + logdelta - ql;
        }
    }
    float tot = blockReduceSum(acc, sm);
    if (threadIdx.x == 0) atomicAdd(&g_scalars[1], 0.5f * tot);
}

// ---------------- generic tiled GEMM (NN, split-K atomic, opt fused bias) ---
__global__ void gemmNN(const float* __restrict__ A, const float* __restrict__ B,
                       float* __restrict__ C, int M, int N, int Kd, int kchunk,
                       const float* __restrict__ bias, int relu) {
    __shared__ float As[16][64];
    __shared__ float Bs[16][64];
    int tid = threadIdx.x;
    int tx = tid & 15, ty = tid >> 4;
    int row0 = blockIdx.y * 64, col0 = blockIdx.x * 64;
    int kbeg = blockIdx.z * kchunk;
    int kend = min(Kd, kbeg + kchunk);
    int aRow = tid >> 2, aCol = (tid & 3) << 2;
    int bRow = tid >> 4, bCol = (tid & 15) << 2;
    float acc[4][4] = {};
    for (int k0 = kbeg; k0 < kend; k0 += 16) {
#pragma unroll
        for (int i = 0; i < 4; i++) {
            int kk = k0 + aCol + i, r = row0 + aRow;
            As[aCol + i][aRow] = (r < M && kk < kend) ? A[(size_t)r * Kd + kk] : 0.f;
        }
#pragma unroll
        for (int i = 0; i < 4; i++) {
            int kk = k0 + bRow, n = col0 + bCol + i;
            Bs[bRow][bCol + i] = (n < N && kk < kend) ? B[(size_t)kk * N + n] : 0.f;
        }
        __syncthreads();
#pragma unroll
        for (int kk = 0; kk < 16; kk++) {
            float a[4], b[4];
#pragma unroll
            for (int i = 0; i < 4; i++) a[i] = As[kk][ty * 4 + i];
#pragma unroll
            for (int j = 0; j < 4; j++) b[j] = Bs[kk][tx * 4 + j];
#pragma unroll
            for (int i = 0; i < 4; i++)
#pragma unroll
                for (int j = 0; j < 4; j++) acc[i][j] = fmaf(a[i], b[j], acc[i][j]);
        }
        __syncthreads();
    }
#pragma unroll
    for (int i = 0; i < 4; i++) {
        int r = row0 + ty * 4 + i;
        if (r >= M) continue;
#pragma unroll
        for (int j = 0; j < 4; j++) {
            int c = col0 + tx * 4 + j;
            if (c >= N) continue;
            if (gridDim.z > 1) atomicAdd(&C[(size_t)r * N + c], acc[i][j]);
            else {
                float v = acc[i][j];
                if (bias) v += bias[c];
                if (relu) v = fmaxf(v, 0.f);
                C[(size_t)r * N + c] = v;
            }
        }
    }
}

// ---------------- bias (+optional relu) -------------------------------------
__global__ void biasActK(float* __restrict__ C, const float* __restrict__ b,
                         int M, int N, int relu) {
    int stride = gridDim.x * blockDim.x;
    for (int i = blockIdx.x * blockDim.x + threadIdx.x; i < M * N; i += stride) {
        float v = C[i] + b[i % N];
        if (relu) v = fmaxf(v, 0.f);
        C[i] = v;
    }
}

// ---------------- LSTM: reg Whh (bf16x2) + smem xw + fast activations -------
__device__ __forceinline__ unsigned ctarank_() {
    unsigned r; asm("mov.u32 %0, %%cluster_ctarank;" : "=r"(r)); return r;
}
__device__ __forceinline__ void cluster_sync_() {
    asm volatile("barrier.cluster.arrive.aligned;" ::: "memory");
    asm volatile("barrier.cluster.wait.aligned;" ::: "memory");
}
__device__ __forceinline__ float sigmoid_fast(float x) {
    return __fdividef(1.f, 1.f + __expf(-x));
}
__device__ __forceinline__ float tanh_fast(float x) {
    return __fdividef(2.f, 1.f + __expf(-2.f * x)) - 1.f;
}

__global__ void __launch_bounds__(512, 1) __cluster_dims__(4, 1, 1)
lstmK(const float* __restrict__ xw, const float* __restrict__ Whh,
      float* __restrict__ hs) {
    __shared__ float xws[10000];               // this CTA's 50x200 xw slice (40KB)
    __shared__ __align__(16) float hA[256];
    __shared__ __align__(16) float hB[256];
    __shared__ float pbuf[512];
    int tid = threadIdx.x;
    unsigned rank = ctarank_();

    int j = tid % 200;
    int half = (tid < 400) ? (tid / 200) : 0;
    int col = (j / 50) * 200 + (int)rank * 50 + (j % 50);

    uint32_t w2[50];
    if (tid < 400) {
#pragma unroll
        for (int i = 0; i < 50; i++) {
            float f0 = Whh[(size_t)(half * 100 + 2 * i) * 800 + col];
            float f1 = Whh[(size_t)(half * 100 + 2 * i + 1) * 800 + col];
            __nv_bfloat162 b2 = __floats2bfloat162_rn(f0, f1);
            w2[i] = *(uint32_t*)&b2;
        }
    }
    for (int idx = tid; idx < 10000; idx += 512) {
        int t = idx / 200, jl = idx - t * 200;
        int cj = (jl / 50) * 200 + (int)rank * 50 + (jl % 50);
        xws[idx] = xw[t * 800 + cj];
    }
    if (tid < 200) hA[tid] = 0.f;
    float c = 0.f;
    __syncthreads();
    cluster_sync_();

    const uint32_t hAaddr = (uint32_t)__cvta_generic_to_shared(hA);
    const uint32_t hBaddr = (uint32_t)__cvta_generic_to_shared(hB);

    for (int t = 0; t < Tt; t++) {
        const float4* hv4 = (const float4*)((t & 1) ? hB : hA);
        const uint32_t hwaddr = (t & 1) ? hAaddr : hBaddr;
        if (tid < 400) {
            float p0 = 0.f, p1 = 0.f;
            const float4* hh4 = hv4 + half * 25;
#pragma unroll
            for (int i = 0; i < 25; i++) {
                float4 hh = hh4[i];
                uint32_t wa = w2[2 * i], wb = w2[2 * i + 1];
                p0 = fmaf(hh.x, __int_as_float(wa << 16), p0);
                p1 = fmaf(hh.y, __int_as_float(wa & 0xffff0000u), p1);
                p0 = fmaf(hh.z, __int_as_float(wb << 16), p0);
                p1 = fmaf(hh.w, __int_as_float(wb & 0xffff0000u), p1);
            }
            pbuf[tid] = p0 + p1;
        }
        __syncthreads();
        if (tid < 50) {
            int base = t * 200;
            float gi = xws[base + tid]       + pbuf[tid]       + pbuf[tid + 200];
            float gf = xws[base + 50 + tid]  + pbuf[50 + tid]  + pbuf[250 + tid];
            float gg = xws[base + 100 + tid] + pbuf[100 + tid] + pbuf[300 + tid];
            float go = xws[base + 150 + tid] + pbuf[150 + tid] + pbuf[350 + tid];
            c = sigmoid_fast(gf) * c + sigmoid_fast(gi) * tanh_fast(gg);
            float h2 = sigmoid_fast(go) * tanh_fast(c);
            int e = (int)rank * 50 + tid;
            hs[t * 200 + e] = h2;
            uint32_t la = hwaddr + (uint32_t)(e * 4);
#pragma unroll
            for (unsigned r2 = 0; r2 < 4; r2++) {
                uint32_t ra;
                asm volatile("mapa.shared::cluster.u32 %0, %1, %2;"
                             : "=r"(ra) : "r"(la), "r"(r2));
                asm volatile("st.shared::cluster.f32 [%0], %1;"
                             :: "r"(ra), "f"(h2) : "memory");
            }
        }
        cluster_sync_();
    }
}

// ---------------- eta scan: only the 50x50 recurrence is sequential ---------
__global__ void etaScanK(const float* __restrict__ projMu, const float* __restrict__ projLs,
                         const float* __restrict__ Wmu, const float* __restrict__ Wls) {
    __shared__ float sWm[2500], sWl[2500];
    __shared__ float eta[50], muv[50], lsv[50], red[50];
    __shared__ float klacc;
    int tid = threadIdx.x;   // 128
    for (int i = tid; i < 2500; i += 128) {
        sWm[i] = Wmu[10000 + i];
        sWl[i] = Wls[10000 + i];
    }
    if (tid < 50) eta[tid] = 0.f;
    if (tid == 0) klacc = 0.f;
    const float logdelta = logf(0.005f);
    __syncthreads();
    for (int t = 0; t < Tt; t++) {
        if (tid < 50) {
            float m = projMu[t * 50 + tid];
#pragma unroll 10
            for (int jj = 0; jj < 50; jj++) m = fmaf(eta[jj], sWm[jj * 50 + tid], m);
            muv[tid] = m;
        } else if (tid >= 64 && tid < 114) {
            int k = tid - 64;
            float m = projLs[t * 50 + k];
#pragma unroll 10
            for (int jj = 0; jj < 50; jj++) m = fmaf(eta[jj], sWl[jj * 50 + k], m);
            lsv[k] = m;
        }
        __syncthreads();
        if (tid < 50) {
            float pls = (t == 0) ? 0.f : logdelta;
            float mu = muv[tid], ls = lsv[tid], ep = eta[tid];
            float dm = mu - ep;
            red[tid] = (__expf(ls) + dm * dm) / (__expf(pls) + 1e-6f) - 1.f + pls - ls;
            g_etas[t * 50 + tid] = mu;
            eta[tid] = mu;
        }
        __syncthreads();
        if (tid == 0) {
            float s = 0.f;
            for (int i = 0; i < 50; i++) s += red[i];
            klacc += 0.5f * s;
        }
        __syncthreads();
    }
    if (tid == 0) g_scalars[2] = klacc;
}

// ---------------- build cat = [bows | eta_td] -------------------------------
__global__ void buildCatK(const float* __restrict__ bows, const int* __restrict__ times) {
    int stride = gridDim.x * blockDim.x;
    for (int i = blockIdx.x * blockDim.x + threadIdx.x; i < Dd * 3050; i += stride) {
        int d = i / 3050, j = i % 3050;
        g_cat[i] = (j < Vv) ? bows[d * Vv + j] : g_etas[times[d] * 50 + (j - Vv)];
    }
}

// ---------------- theta softmax + kl_theta ----------------------------------
__global__ void thetaKlK(const int* __restrict__ times) {
    int d = blockIdx.x, tid = threadIdx.x;
    __shared__ float sm[64];
    float mu = (tid < 50) ? g_muth[d * 50 + tid] : -1e30f;
    sm[tid] = mu; __syncthreads();
    for (int off = 32; off > 0; off >>= 1) {
        if (tid < off) sm[tid] = fmaxf(sm[tid], sm[tid + off]);
        __syncthreads();
    }
    float m = sm[0]; __syncthreads();
    float e = (tid < 50) ? __expf(mu - m) : 0.f;
    sm[tid] = e; __syncthreads();
    for (int off = 32; off > 0; off >>= 1) {
        if (tid < off) sm[tid] += sm[tid + off];
        __syncthreads();
    }
    float Z = sm[0]; __syncthreads();
    if (tid < 50) g_theta[d * 50 + tid] = e / Z;
    float term = 0.f;
    if (tid < 50) {
        float ls = g_lsth[d * 50 + tid];
        float et = g_etas[times[d] * 50 + tid];
        float dm = mu - et;
        term = (__expf(ls) + dm * dm) / (1.f + 1e-6f) - 1.f - ls;
    }
    sm[tid] = term; __syncthreads();
    for (int off = 32; off > 0; off >>= 1) {
        if (tid < off) sm[tid] += sm[tid + off];
        __syncthreads();
    }
    if (tid == 0) atomicAdd(&g_scalars[3], 0.5f * sm[0]);
}

// ---------------- lik + nll (bf16 P, 4 v per thread) ------------------------
__global__ void likNllK(const float* __restrict__ bows) {
    __shared__ float w[50];
    __shared__ float sm[256];
    int d = blockIdx.y, tid = threadIdx.x;
    if (tid < 50) w[tid] = g_theta[d * 50 + tid] / g_S[d * 50 + tid];
    __syncthreads();
    int v0 = (blockIdx.x * 256 + tid) * 4;
    float acc = 0.f;
    if (v0 < Vv) {
        const __nv_bfloat16* Pr = g_Pbf + (size_t)d * 50 * Vv + v0;
        float l0 = 0.f, l1 = 0.f, l2 = 0.f, l3 = 0.f;
#pragma unroll 10
        for (int k = 0; k < 50; k++) {
            uint2 u = *(const uint2*)&Pr[(size_t)k * Vv];
            __nv_bfloat162 pa = *(__nv_bfloat162*)&u.x;
            __nv_bfloat162 pb = *(__nv_bfloat162*)&u.y;
            float wk = w[k];
            l0 = fmaf(wk, __low2float(pa), l0);
            l1 = fmaf(wk, __high2float(pa), l1);
            l2 = fmaf(wk, __low2float(pb), l2);
            l3 = fmaf(wk, __high2float(pb), l3);
        }
        float4 bw = *(const float4*)&bows[(size_t)d * Vv + v0];
        acc = __logf(l0 + 1e-6f) * bw.x + __logf(l1 + 1e-6f) * bw.y
            + __logf(l2 + 1e-6f) * bw.z + __logf(l3 + 1e-6f) * bw.w;
    }
    float tot = blockReduceSum(acc, sm);
    if (tid == 0) atomicAdd(&g_scalars[0], tot);
}

__global__ void finalizeK(float* __restrict__ out) {
    if (threadIdx.x == 0) {
        out[0] = -g_scalars[0];
        out[1] = g_scalars[1];
        out[2] = g_scalars[2];
        out[3] = g_scalars[3];
    }
}

// ---------------- host orchestration: forked two-stream graph ---------------
extern "C" void kernel_launch(void* const* d_in, const int* in_sizes, int n_in,
                              void* d_out, int out_size) {
    const float* bows    = (const float*)d_in[0];
    const float* rnn_inp = (const float*)d_in[1];
    const int*   times   = (const int*)d_in[2];
    const int*   sources = (const int*)d_in[3];
    const float* rho     = (const float*)d_in[4];
    const float* lam     = (const float*)d_in[5];
    const float* mu_q    = (const float*)d_in[6];
    const float* ls_q    = (const float*)d_in[7];
    const float* W_t1    = (const float*)d_in[8];
    const float* b_t1    = (const float*)d_in[9];
    const float* W_t2    = (const float*)d_in[10];
    const float* b_t2    = (const float*)d_in[11];
    const float* W_mu_th = (const float*)d_in[12];
    const float* b_mu_th = (const float*)d_in[13];
    const float* W_ls_th = (const float*)d_in[14];
    const float* b_ls_th = (const float*)d_in[15];
    const float* W_em    = (const float*)d_in[16];
    const float* b_em    = (const float*)d_in[17];
    const float* Wih0    = (const float*)d_in[18];
    const float* Whh0    = (const float*)d_in[19];
    const float* bl0     = (const float*)d_in[20];
    const float* Wih1    = (const float*)d_in[21];
    const float* Whh1    = (const float*)d_in[22];
    const float* bl1     = (const float*)d_in[23];
    const float* W_mu_e  = (const float*)d_in[24];
    const float* b_mu_e  = (const float*)d_in[25];
    const float* W_ls_e  = (const float*)d_in[26];
    const float* b_ls_e  = (const float*)d_in[27];

    float *pX, *pXw0, *pXw1, *pHs0, *pHs1, *pCat, *pH1, *pH2, *pMuth, *pLsth, *pS;
    float *pPm, *pPl;
    __nv_bfloat16 *pAbf, *pRhoBf, *pPbf;
    cudaGetSymbolAddress((void**)&pX, g_x);
    cudaGetSymbolAddress((void**)&pXw0, g_xw0);
    cudaGetSymbolAddress((void**)&pXw1, g_xw1);
    cudaGetSymbolAddress((void**)&pHs0, g_hs0);
    cudaGetSymbolAddress((void**)&pHs1, g_hs1);
    cudaGetSymbolAddress((void**)&pCat, g_cat);
    cudaGetSymbolAddress((void**)&pH1, g_h1);
    cudaGetSymbolAddress((void**)&pH2, g_h2);
    cudaGetSymbolAddress((void**)&pMuth, g_muth);
    cudaGetSymbolAddress((void**)&pLsth, g_lsth);
    cudaGetSymbolAddress((void**)&pS, g_S);
    cudaGetSymbolAddress((void**)&pPm, g_projMu);
    cudaGetSymbolAddress((void**)&pPl, g_projLs);
    cudaGetSymbolAddress((void**)&pAbf, g_Abf);
    cudaGetSymbolAddress((void**)&pRhoBf, g_rhoBf);
    cudaGetSymbolAddress((void**)&pPbf, g_Pbf);

    cudaFuncSetAttribute(gemmExpMMA, cudaFuncAttributeMaxDynamicSharedMemorySize, GEMM_SMEM);

    // streams/events created once (host objects; no device memory)
    static cudaStream_t sA = nullptr, sB = nullptr;
    static cudaEvent_t evFork = nullptr, evA = nullptr, evB = nullptr;
    if (sA == nullptr) {
        cudaStreamCreateWithFlags(&sA, cudaStreamNonBlocking);
        cudaStreamCreateWithFlags(&sB, cudaStreamNonBlocking);
        cudaEventCreateWithFlags(&evFork, cudaEventDisableTiming);
        cudaEventCreateWithFlags(&evA, cudaEventDisableTiming);
        cudaEventCreateWithFlags(&evB, cudaEventDisableTiming);
    }

    // prologue on the captured (legacy) stream
    zeroAllK<<<256, 256>>>();
    cudaEventRecord(evFork, 0);
    cudaStreamWaitEvent(sA, evFork, 0);
    cudaStreamWaitEvent(sB, evFork, 0);

    // ---- Path A (stream sA): einsum chain + klAlpha ----
    buildABfK<<<2048, 256, 0, sA>>>(mu_q, lam, times, sources);
    rhoBfK<<<512, 256, 0, sA>>>(rho);
    gemmExpMMA<<<dim3(24, 100), 256, GEMM_SMEM, sA>>>(pAbf, pRhoBf, pPbf, pS);
    klAlphaK<<<256, 256, 0, sA>>>(mu_q, ls_q);

    // ---- Path B (stream sB): LSTM -> eta -> theta MLP ----
    gemmNN<<<dim3(4, 1, 8), 256, 0, sB>>>(rnn_inp, W_em, pX, 50, 200, 3000, 384, nullptr, 0);
    biasActK<<<40, 256, 0, sB>>>(pX, b_em, 50, 200, 0);
    gemmNN<<<dim3(13, 1, 1), 256, 0, sB>>>(pX, Wih0, pXw0, 50, 800, 200, 200, bl0, 0);
    lstmK<<<4, 512, 0, sB>>>(pXw0, Whh0, pHs0);
    gemmNN<<<dim3(13, 1, 1), 256, 0, sB>>>(pHs0, Wih1, pXw1, 50, 800, 200, 200, bl1, 0);
    lstmK<<<4, 512, 0, sB>>>(pXw1, Whh1, pHs1);
    gemmNN<<<dim3(1, 1, 1), 256, 0, sB>>>(pHs1, W_mu_e, pPm, 50, 50, 200, 200, b_mu_e, 0);
    gemmNN<<<dim3(1, 1, 1), 256, 0, sB>>>(pHs1, W_ls_e, pPl, 50, 50, 200, 200, b_ls_e, 0);
    etaScanK<<<1, 128, 0, sB>>>(pPm, pPl, W_mu_e, W_ls_e);
    buildCatK<<<1024, 256, 0, sB>>>(bows, times);
    gemmNN<<<dim3(13, 4, 4), 256, 0, sB>>>(pCat, W_t1, pH1, 256, 800, 3050, 768, nullptr, 0);
    biasActK<<<800, 256, 0, sB>>>(pH1, b_t1, 256, 800, 1);
    gemmNN<<<dim3(13, 4, 1), 256, 0, sB>>>(pH1, W_t2, pH2, 256, 800, 800, 800, b_t2, 1);
    gemmNN<<<dim3(1, 4, 8), 256, 0, sB>>>(pH2, W_mu_th, pMuth, 256, 50, 800, 112, nullptr, 0);
    biasActK<<<50, 256, 0, sB>>>(pMuth, b_mu_th, 256, 50, 0);
    gemmNN<<<dim3(1, 4, 8), 256, 0, sB>>>(pH2, W_ls_th, pLsth, 256, 50, 800, 112, nullptr, 0);
    biasActK<<<50, 256, 0, sB>>>(pLsth, b_ls_th, 256, 50, 0);
    thetaKlK<<<256, 64, 0, sB>>>(times);

    // ---- join on legacy stream ----
    cudaEventRecord(evA, sA);
    cudaEventRecord(evB, sB);
    cudaStreamWaitEvent(0, evA, 0);
    cudaStreamWaitEvent(0, evB, 0);

    likNllK<<<dim3(3, 256), 256>>>(bows);
    finalizeK<<<1, 32>>>((float*)d_out);
}